// round 1
// baseline (speedup 1.0000x reference)
#include <cuda_runtime.h>

#define BATCH 16
#define HEADS 8
#define DH 32
#define LSP 1024
#define CIN 256

// scratch: q, k(+PE), v laid out as [b*heads + h][d][l]
__device__ float g_q[BATCH * HEADS * DH * LSP];
__device__ float g_k[BATCH * HEADS * DH * LSP];
__device__ float g_v[BATCH * HEADS * DH * LSP];

// ---------------------------------------------------------------------------
// Kernel 1: grouped 1x1 conv -> q,k,v ; sine positional encoding fused into k
// grid (L/64, heads, B), 256 threads
// ---------------------------------------------------------------------------
__global__ __launch_bounds__(256) void qkv_kernel(
    const float* __restrict__ x,
    const float* __restrict__ wq,
    const float* __restrict__ wk,
    const float* __restrict__ wv)
{
    __shared__ float sW[3][32][32];   // [mat][o][c]
    __shared__ float sx[32][64];      // [c][l]

    const int l0  = blockIdx.x * 64;
    const int h   = blockIdx.y;
    const int b   = blockIdx.z;
    const int tid = threadIdx.x;

    // load the three 32x32 weight blocks for this head
    for (int i = tid; i < 1024; i += 256) {
        int o = i >> 5, c = i & 31;
        int gi = (h * 32 + o) * 32 + c;
        sW[0][o][c] = wq[gi];
        sW[1][o][c] = wk[gi];
        sW[2][o][c] = wv[gi];
    }
    // load x tile: 32 channels x 64 positions (coalesced by 64)
    for (int i = tid; i < 2048; i += 256) {
        int c = i >> 6, l = i & 63;
        sx[c][l] = x[((b * CIN + h * 32 + c) * LSP) + l0 + l];
    }
    __syncthreads();

    const int l  = tid & 63;     // warp-contiguous l -> conflict-free sx reads
    const int og = tid >> 6;     // 0..3 ; whole warp shares og -> W broadcast
    const long base = ((long)(b * HEADS + h) * DH) * LSP;

    #pragma unroll
    for (int o2 = 0; o2 < 8; o2++) {
        const int o = og * 8 + o2;
        float aq = 0.f, ak = 0.f, av = 0.f;
        #pragma unroll
        for (int c = 0; c < 32; c++) {
            const float xv = sx[c][l];
            aq = fmaf(sW[0][o][c], xv, aq);
            ak = fmaf(sW[1][o][c], xv, ak);
            av = fmaf(sW[2][o][c], xv, av);
        }
        // sine PE for k: global channel g = h*32+o, pair index uses g & ~1
        const int gch = h * 32 + o;
        const float div = expf(-9.210340371976184f * (float)(gch & ~1) *
                               (1.0f / 256.0f));
        const float ang = div * (float)(l0 + l);
        const float pe  = (gch & 1) ? cosf(ang) : sinf(ang);

        const long idx = base + (long)o * LSP + l0 + l;
        g_q[idx] = aq;
        g_k[idx] = ak + pe;
        g_v[idx] = av;
    }
}

// ---------------------------------------------------------------------------
// Kernel 2: flash attention. One thread per query; K/V tiles of 32 keys in
// smem read as float4 broadcasts (4 FFMA per LDS.128).
// grid (L/256, B*heads), 256 threads
// ---------------------------------------------------------------------------
__global__ __launch_bounds__(256, 2) void attn_kernel(float* __restrict__ out)
{
    __shared__ float4 sk[32][8];   // [d][lk/4]
    __shared__ float4 sv[32][8];

    const int bh = blockIdx.y;                           // 0..127
    const int lq = blockIdx.x * 256 + threadIdx.x;       // query position
    const float* __restrict__ qp = g_q + (long)bh * DH * LSP;
    const float* __restrict__ kp = g_k + (long)bh * DH * LSP;
    const float* __restrict__ vp = g_v + (long)bh * DH * LSP;

    float q[32], o[32], s[32];
    #pragma unroll
    for (int d = 0; d < 32; d++) {
        q[d] = qp[d * LSP + lq];   // coalesced: consecutive lq per warp
        o[d] = 0.f;
    }
    float m = -1e30f, lsum = 0.f;

    for (int kt = 0; kt < 32; kt++) {
        __syncthreads();
        // stage K,V tile (32 d x 32 lk each); coalesced 32-float rows
        {
            const int tid = threadIdx.x;
            float* skf = (float*)sk;
            float* svf = (float*)sv;
            #pragma unroll
            for (int i = tid; i < 1024; i += 256) {
                const int d = i >> 5, lk = i & 31;
                skf[d * 32 + lk] = kp[d * LSP + kt * 32 + lk];
                svf[d * 32 + lk] = vp[d * LSP + kt * 32 + lk];
            }
        }
        __syncthreads();

        // scores: s[lk] = sum_d q[d]*K[d][lk]
        #pragma unroll
        for (int j = 0; j < 32; j++) s[j] = 0.f;
        #pragma unroll
        for (int d = 0; d < 32; d++) {
            const float qd = q[d];
            #pragma unroll
            for (int jv = 0; jv < 8; jv++) {
                const float4 kk = sk[d][jv];
                s[jv * 4 + 0] = fmaf(qd, kk.x, s[jv * 4 + 0]);
                s[jv * 4 + 1] = fmaf(qd, kk.y, s[jv * 4 + 1]);
                s[jv * 4 + 2] = fmaf(qd, kk.z, s[jv * 4 + 2]);
                s[jv * 4 + 3] = fmaf(qd, kk.w, s[jv * 4 + 3]);
            }
        }

        // online softmax update
        float mt = m;
        #pragma unroll
        for (int j = 0; j < 32; j++) mt = fmaxf(mt, s[j]);
        const float corr = __expf(m - mt);
        m = mt;
        lsum *= corr;
        #pragma unroll
        for (int d = 0; d < 32; d++) o[d] *= corr;
        #pragma unroll
        for (int j = 0; j < 32; j++) {
            s[j] = __expf(s[j] - mt);
            lsum += s[j];
        }

        // o[d] += sum_lk p[lk] * V[d][lk]
        #pragma unroll
        for (int d = 0; d < 32; d++) {
            float acc = o[d];
            #pragma unroll
            for (int jv = 0; jv < 8; jv++) {
                const float4 vv = sv[d][jv];
                acc = fmaf(s[jv * 4 + 0], vv.x, acc);
                acc = fmaf(s[jv * 4 + 1], vv.y, acc);
                acc = fmaf(s[jv * 4 + 2], vv.z, acc);
                acc = fmaf(s[jv * 4 + 3], vv.w, acc);
            }
            o[d] = acc;
        }
    }

    const float inv = 1.0f / lsum;
    #pragma unroll
    for (int d = 0; d < 32; d++)
        out[(long)bh * DH * LSP + (long)d * LSP + lq] = o[d] * inv;
}

// ---------------------------------------------------------------------------
extern "C" void kernel_launch(void* const* d_in, const int* in_sizes, int n_in,
                              void* d_out, int out_size)
{
    const float* x  = (const float*)d_in[0];
    const float* wq = (const float*)d_in[1];
    const float* wk = (const float*)d_in[2];
    const float* wv = (const float*)d_in[3];
    float* out = (float*)d_out;

    dim3 g1(LSP / 64, HEADS, BATCH);
    qkv_kernel<<<g1, 256>>>(x, wq, wk, wv);

    dim3 g2(LSP / 256, BATCH * HEADS);
    attn_kernel<<<g2, 256>>>(out);
}

// round 3
// speedup vs baseline: 8.2340x; 8.2340x over previous
#include <cuda_runtime.h>
#include <cuda_fp16.h>
#include <cstdint>

#define BATCH 16
#define HEADS 8
#define DH 32
#define LSP 1024
#define CIN 256
#define BH_N (BATCH*HEADS)
#define QT 128            // queries per CTA (8 warps x 16)
#define KTL 128           // keys per tile
#define NKT (LSP/KTL)
#define KPAD 40           // K smem row stride (halves)
#define VPAD 136          // V smem row stride (halves)

// fp16 staging: q,k as [bh][l][d]; v as [bh][d][l]
__device__ __half g_qh[(size_t)BH_N * LSP * DH];
__device__ __half g_kh[(size_t)BH_N * LSP * DH];
__device__ __half g_vh[(size_t)BH_N * DH * LSP];

// ---------------------------------------------------------------------------
// Kernel 1: grouped 1x1 conv -> q,k,v (fp16); sine PE fused into k
// ---------------------------------------------------------------------------
__global__ __launch_bounds__(256) void qkv_kernel(
    const float* __restrict__ x,
    const float* __restrict__ wq,
    const float* __restrict__ wk,
    const float* __restrict__ wv)
{
    __shared__ float sW[3][32][32];
    __shared__ float sx[32][64];

    const int l0  = blockIdx.x * 64;
    const int h   = blockIdx.y;
    const int b   = blockIdx.z;
    const int tid = threadIdx.x;

    for (int i = tid; i < 1024; i += 256) {
        int o = i >> 5, c = i & 31;
        int gi = (h * 32 + o) * 32 + c;
        sW[0][o][c] = wq[gi];
        sW[1][o][c] = wk[gi];
        sW[2][o][c] = wv[gi];
    }
    for (int i = tid; i < 2048; i += 256) {
        int c = i >> 6, l = i & 63;
        sx[c][l] = x[((b * CIN + h * 32 + c) * LSP) + l0 + l];
    }
    __syncthreads();

    const int l  = tid & 63;
    const int og = tid >> 6;
    const int bh = b * HEADS + h;

    __align__(16) __half hq[8];
    __align__(16) __half hk[8];

    #pragma unroll
    for (int o2 = 0; o2 < 8; o2++) {
        const int o = og * 8 + o2;
        float aq = 0.f, ak = 0.f, av = 0.f;
        #pragma unroll
        for (int c = 0; c < 32; c++) {
            const float xv = sx[c][l];
            aq = fmaf(sW[0][o][c], xv, aq);
            ak = fmaf(sW[1][o][c], xv, ak);
            av = fmaf(sW[2][o][c], xv, av);
        }
        const int gch = h * 32 + o;
        const float div = expf(-9.210340371976184f * (float)(gch & ~1) *
                               (1.0f / 256.0f));
        const float ang = div * (float)(l0 + l);
        const float pe  = (gch & 1) ? cosf(ang) : sinf(ang);

        hq[o2] = __float2half(aq);
        hk[o2] = __float2half(ak + pe);
        g_vh[((size_t)bh * DH + o) * LSP + l0 + l] = __float2half(av);
    }
    const size_t row = ((size_t)bh * LSP + l0 + l) * DH + og * 8;
    *(uint4*)(g_qh + row) = *(const uint4*)hq;
    *(uint4*)(g_kh + row) = *(const uint4*)hk;
}

// ---------------------------------------------------------------------------
// HMMA helper: mma.sync m16n8k16 row.col f32.f16.f16.f32 (sm_80 baseline)
// ---------------------------------------------------------------------------
__device__ __forceinline__ void mma16816(
    float& d0, float& d1, float& d2, float& d3,
    uint32_t a0, uint32_t a1, uint32_t a2, uint32_t a3,
    uint32_t b0, uint32_t b1)
{
    asm volatile(
        "mma.sync.aligned.m16n8k16.row.col.f32.f16.f16.f32 "
        "{%0,%1,%2,%3}, {%4,%5,%6,%7}, {%8,%9}, {%0,%1,%2,%3};"
        : "+f"(d0), "+f"(d1), "+f"(d2), "+f"(d3)
        : "r"(a0), "r"(a1), "r"(a2), "r"(a3), "r"(b0), "r"(b1));
}

// ---------------------------------------------------------------------------
// Kernel 2: register-fragment flash attention with HMMA.
// 8 warps; warp = 16 query rows x dh 32. K tile 128 keys in smem.
// ---------------------------------------------------------------------------
__global__ __launch_bounds__(256, 2) void attn_kernel(float* __restrict__ out)
{
    __shared__ __half Ks[KTL][KPAD];   // [key][d], padded rows (80B)
    __shared__ __half Vs[DH][VPAD];    // [d][key], padded rows (272B)

    const int tid  = threadIdx.x;
    const int wid  = tid >> 5;
    const int lane = tid & 31;
    const int gid  = lane >> 2;   // 0..7
    const int tig  = lane & 3;    // 0..3
    const int bh   = blockIdx.y;
    const int q0   = blockIdx.x * QT + wid * 16;

    // Q fragments: 2 k-chunks (d 0-15, 16-31), 4 regs each
    uint32_t qa[8];
    {
        const __half* qb = g_qh + ((size_t)bh * LSP + q0) * DH;
        #pragma unroll
        for (int kk = 0; kk < 2; kk++) {
            qa[kk*4+0] = *(const uint32_t*)(qb + (gid    ) * DH + kk*16     + tig*2);
            qa[kk*4+1] = *(const uint32_t*)(qb + (gid + 8) * DH + kk*16     + tig*2);
            qa[kk*4+2] = *(const uint32_t*)(qb + (gid    ) * DH + kk*16 + 8 + tig*2);
            qa[kk*4+3] = *(const uint32_t*)(qb + (gid + 8) * DH + kk*16 + 8 + tig*2);
        }
    }

    float o[16];
    #pragma unroll
    for (int i = 0; i < 16; i++) o[i] = 0.f;
    float m0 = -1e30f, m1 = -1e30f, l0 = 0.f, l1 = 0.f;

    for (int kt = 0; kt < NKT; kt++) {
        __syncthreads();
        // stage K tile: 128 rows x 32 halves (two uint4 per thread)
        {
            const int r = tid >> 1, c = (tid & 1) * 16;
            const uint4* src = (const uint4*)(g_kh +
                ((size_t)bh * LSP + (size_t)kt * KTL + r) * DH + c);
            *(uint4*)&Ks[r][c]     = src[0];
            *(uint4*)&Ks[r][c + 8] = src[1];
        }
        // stage V tile: 32 rows(d) x 128 halves
        {
            #pragma unroll
            for (int i = tid; i < 512; i += 256) {
                const int r = i >> 4, c = (i & 15) * 8;
                *(uint4*)&Vs[r][c] = *(const uint4*)(g_vh +
                    ((size_t)bh * DH + r) * LSP + (size_t)kt * KTL + c);
            }
        }
        __syncthreads();

        // ---- S = Q x K^T : 16 n-chunks of 8 keys, 2 k-steps each ----
        float s[16][4];
        #pragma unroll
        for (int j = 0; j < 16; j++) {
            s[j][0] = s[j][1] = s[j][2] = s[j][3] = 0.f;
            const __half* kr = &Ks[j * 8 + gid][0];
            uint32_t b0 = *(const uint32_t*)(kr + tig*2);
            uint32_t b1 = *(const uint32_t*)(kr + tig*2 + 8);
            mma16816(s[j][0], s[j][1], s[j][2], s[j][3],
                     qa[0], qa[1], qa[2], qa[3], b0, b1);
            b0 = *(const uint32_t*)(kr + 16 + tig*2);
            b1 = *(const uint32_t*)(kr + 24 + tig*2);
            mma16816(s[j][0], s[j][1], s[j][2], s[j][3],
                     qa[4], qa[5], qa[6], qa[7], b0, b1);
        }

        // ---- online softmax ----
        float nm0 = m0, nm1 = m1;
        #pragma unroll
        for (int j = 0; j < 16; j++) {
            nm0 = fmaxf(nm0, fmaxf(s[j][0], s[j][1]));
            nm1 = fmaxf(nm1, fmaxf(s[j][2], s[j][3]));
        }
        nm0 = fmaxf(nm0, __shfl_xor_sync(0xffffffffu, nm0, 1));
        nm0 = fmaxf(nm0, __shfl_xor_sync(0xffffffffu, nm0, 2));
        nm1 = fmaxf(nm1, __shfl_xor_sync(0xffffffffu, nm1, 1));
        nm1 = fmaxf(nm1, __shfl_xor_sync(0xffffffffu, nm1, 2));
        const float c0 = __expf(m0 - nm0);
        const float c1 = __expf(m1 - nm1);
        m0 = nm0; m1 = nm1;
        l0 *= c0;  l1 *= c1;
        #pragma unroll
        for (int nc = 0; nc < 4; nc++) {
            o[nc*4+0] *= c0; o[nc*4+1] *= c0;
            o[nc*4+2] *= c1; o[nc*4+3] *= c1;
        }
        // exp + pack P in place (s[j][0] <- half2(e00,e01), s[j][1] <- half2(e10,e11))
        #pragma unroll
        for (int j = 0; j < 16; j++) {
            float e00 = __expf(s[j][0] - m0);
            float e01 = __expf(s[j][1] - m0);
            float e10 = __expf(s[j][2] - m1);
            float e11 = __expf(s[j][3] - m1);
            l0 += e00 + e01;
            l1 += e10 + e11;
            __half2 h0 = __floats2half2_rn(e00, e01);
            __half2 h1 = __floats2half2_rn(e10, e11);
            s[j][0] = __uint_as_float(*(uint32_t*)&h0);
            s[j][1] = __uint_as_float(*(uint32_t*)&h1);
        }

        // ---- O += P x V : 4 n-chunks (dh), 8 k-chunks (keys) ----
        #pragma unroll
        for (int nc = 0; nc < 4; nc++) {
            const __half* vr = &Vs[nc * 8 + gid][0];
            float& d0 = o[nc*4+0];
            float& d1 = o[nc*4+1];
            float& d2 = o[nc*4+2];
            float& d3 = o[nc*4+3];
            #pragma unroll
            for (int c = 0; c < 8; c++) {
                uint32_t a0 = __float_as_uint(s[2*c    ][0]);
                uint32_t a1 = __float_as_uint(s[2*c    ][1]);
                uint32_t a2 = __float_as_uint(s[2*c + 1][0]);
                uint32_t a3 = __float_as_uint(s[2*c + 1][1]);
                uint32_t b0 = *(const uint32_t*)(vr + c*16 + tig*2);
                uint32_t b1 = *(const uint32_t*)(vr + c*16 + 8 + tig*2);
                mma16816(d0, d1, d2, d3, a0, a1, a2, a3, b0, b1);
            }
        }
    }

    // reduce lsum across quad, normalize, write out
    l0 += __shfl_xor_sync(0xffffffffu, l0, 1);
    l0 += __shfl_xor_sync(0xffffffffu, l0, 2);
    l1 += __shfl_xor_sync(0xffffffffu, l1, 1);
    l1 += __shfl_xor_sync(0xffffffffu, l1, 2);
    const float inv0 = 1.0f / l0;
    const float inv1 = 1.0f / l1;

    float* ob = out + (size_t)bh * DH * LSP;
    #pragma unroll
    for (int nc = 0; nc < 4; nc++) {
        const int d = nc * 8 + tig * 2;
        ob[(size_t)(d    ) * LSP + q0 + gid    ] = o[nc*4+0] * inv0;
        ob[(size_t)(d + 1) * LSP + q0 + gid    ] = o[nc*4+1] * inv0;
        ob[(size_t)(d    ) * LSP + q0 + gid + 8] = o[nc*4+2] * inv1;
        ob[(size_t)(d + 1) * LSP + q0 + gid + 8] = o[nc*4+3] * inv1;
    }
}

// ---------------------------------------------------------------------------
extern "C" void kernel_launch(void* const* d_in, const int* in_sizes, int n_in,
                              void* d_out, int out_size)
{
    const float* x  = (const float*)d_in[0];
    const float* wq = (const float*)d_in[1];
    const float* wk = (const float*)d_in[2];
    const float* wv = (const float*)d_in[3];
    float* out = (float*)d_out;

    dim3 g1(LSP / 64, HEADS, BATCH);
    qkv_kernel<<<g1, 256>>>(x, wq, wk, wv);

    dim3 g2(LSP / QT, BH_N);
    attn_kernel<<<g2, 256>>>(out);
}

// round 4
// speedup vs baseline: 8.6073x; 1.0453x over previous
#include <cuda_runtime.h>
#include <cuda_fp16.h>
#include <cstdint>

#define BATCH 16
#define HEADS 8
#define DH 32
#define LSP 1024
#define CIN 256
#define BH_N (BATCH*HEADS)
#define QT 128            // queries per CTA (8 warps x 16)
#define KTL 128           // keys per tile
#define NKT (LSP/KTL)
#define KPAD 40           // K smem row stride (halves)
#define VPAD 136          // V smem row stride (halves)

// fp16 staging: q,k as [bh][l][d]; v as [bh][d][l]
__device__ __half g_qh[(size_t)BH_N * LSP * DH];
__device__ __half g_kh[(size_t)BH_N * LSP * DH];
__device__ __half g_vh[(size_t)BH_N * DH * LSP];

// ---------------------------------------------------------------------------
// Kernel 1: grouped 1x1 conv -> q,k,v (fp16); sine PE fused into k.
// Fast-math transcendentals (MUFU path), sin/cos computed once per pair.
// ---------------------------------------------------------------------------
__global__ __launch_bounds__(256) void qkv_kernel(
    const float* __restrict__ x,
    const float* __restrict__ wq,
    const float* __restrict__ wk,
    const float* __restrict__ wv)
{
    __shared__ float sW[3][32][32];
    __shared__ float sx[32][64];

    const int l0  = blockIdx.x * 64;
    const int h   = blockIdx.y;
    const int b   = blockIdx.z;
    const int tid = threadIdx.x;

    for (int i = tid; i < 1024; i += 256) {
        int o = i >> 5, c = i & 31;
        int gi = (h * 32 + o) * 32 + c;
        sW[0][o][c] = wq[gi];
        sW[1][o][c] = wk[gi];
        sW[2][o][c] = wv[gi];
    }
    for (int i = tid; i < 2048; i += 256) {
        int c = i >> 6, l = i & 63;
        sx[c][l] = x[((b * CIN + h * 32 + c) * LSP) + l0 + l];
    }
    __syncthreads();

    const int l  = tid & 63;
    const int og = tid >> 6;
    const int bh = b * HEADS + h;
    const float pos = (float)(l0 + l);

    __align__(16) __half hq[8];
    __align__(16) __half hk[8];

    #pragma unroll
    for (int o2 = 0; o2 < 8; o2 += 2) {
        const int oA = og * 8 + o2;      // even channel
        const int oB = oA + 1;           // odd channel
        float aqA = 0.f, akA = 0.f, avA = 0.f;
        float aqB = 0.f, akB = 0.f, avB = 0.f;
        #pragma unroll
        for (int c = 0; c < 32; c++) {
            const float xv = sx[c][l];
            aqA = fmaf(sW[0][oA][c], xv, aqA);
            akA = fmaf(sW[1][oA][c], xv, akA);
            avA = fmaf(sW[2][oA][c], xv, avA);
            aqB = fmaf(sW[0][oB][c], xv, aqB);
            akB = fmaf(sW[1][oB][c], xv, akB);
            avB = fmaf(sW[2][oB][c], xv, avB);
        }
        const int gch = h * 32 + oA;     // even
        const float div = __expf(-0.03597789207803197f * (float)gch);
        float sv, cv;
        __sincosf(div * pos, &sv, &cv);

        hq[o2]     = __float2half(aqA);
        hq[o2 + 1] = __float2half(aqB);
        hk[o2]     = __float2half(akA + sv);
        hk[o2 + 1] = __float2half(akB + cv);
        g_vh[((size_t)bh * DH + oA) * LSP + l0 + l] = __float2half(avA);
        g_vh[((size_t)bh * DH + oB) * LSP + l0 + l] = __float2half(avB);
    }
    const size_t row = ((size_t)bh * LSP + l0 + l) * DH + og * 8;
    *(uint4*)(g_qh + row) = *(const uint4*)hq;
    *(uint4*)(g_kh + row) = *(const uint4*)hk;
}

// ---------------------------------------------------------------------------
// HMMA + LDSM helpers
// ---------------------------------------------------------------------------
__device__ __forceinline__ void mma16816(
    float& d0, float& d1, float& d2, float& d3,
    uint32_t a0, uint32_t a1, uint32_t a2, uint32_t a3,
    uint32_t b0, uint32_t b1)
{
    asm volatile(
        "mma.sync.aligned.m16n8k16.row.col.f32.f16.f16.f32 "
        "{%0,%1,%2,%3}, {%4,%5,%6,%7}, {%8,%9}, {%0,%1,%2,%3};"
        : "+f"(d0), "+f"(d1), "+f"(d2), "+f"(d3)
        : "r"(a0), "r"(a1), "r"(a2), "r"(a3), "r"(b0), "r"(b1));
}

__device__ __forceinline__ void ldsm_x4(uint32_t& r0, uint32_t& r1,
                                        uint32_t& r2, uint32_t& r3,
                                        const void* p)
{
    uint32_t a = (uint32_t)__cvta_generic_to_shared(p);
    asm volatile(
        "ldmatrix.sync.aligned.m8n8.x4.shared.b16 {%0,%1,%2,%3}, [%4];"
        : "=r"(r0), "=r"(r1), "=r"(r2), "=r"(r3) : "r"(a));
}

// ---------------------------------------------------------------------------
// Kernel 2: register-fragment flash attention with HMMA + LDSM.
// 8 warps; warp = 16 query rows x dh 32. K tile 128 keys in smem.
// Row-sums (lsum) computed by an extra MMA chain against B = ones (exact,
// consistent with the fp16 P used for the V product).
// ---------------------------------------------------------------------------
__global__ __launch_bounds__(256, 2) void attn_kernel(float* __restrict__ out)
{
    __shared__ __half Ks[KTL][KPAD];   // [key][d]
    __shared__ __half Vs[DH][VPAD];    // [d][key]

    const int tid  = threadIdx.x;
    const int wid  = tid >> 5;
    const int lane = tid & 31;
    const int gid  = lane >> 2;   // 0..7
    const int tig  = lane & 3;    // 0..3
    const int bh   = blockIdx.y;
    const int q0   = blockIdx.x * QT + wid * 16;
    const uint32_t ONE2 = 0x3C003C00u;   // half2(1.0, 1.0)

    // Q fragments: 2 k-chunks (d 0-15, 16-31), 4 regs each
    uint32_t qa[8];
    {
        const __half* qb = g_qh + ((size_t)bh * LSP + q0) * DH;
        #pragma unroll
        for (int kk = 0; kk < 2; kk++) {
            qa[kk*4+0] = *(const uint32_t*)(qb + (gid    ) * DH + kk*16     + tig*2);
            qa[kk*4+1] = *(const uint32_t*)(qb + (gid + 8) * DH + kk*16     + tig*2);
            qa[kk*4+2] = *(const uint32_t*)(qb + (gid    ) * DH + kk*16 + 8 + tig*2);
            qa[kk*4+3] = *(const uint32_t*)(qb + (gid + 8) * DH + kk*16 + 8 + tig*2);
        }
    }

    float o[16];
    #pragma unroll
    for (int i = 0; i < 16; i++) o[i] = 0.f;
    float m0 = -1e30f, m1 = -1e30f, l0 = 0.f, l1 = 0.f;

    // per-lane LDSM base offsets
    const int krow = lane & 7;                 // row within 8-row block
    const int kcol = ((lane >> 3) & 3) * 8;    // 8-half column block

    for (int kt = 0; kt < NKT; kt++) {
        __syncthreads();
        // stage K tile: 128 rows x 32 halves
        {
            const int r = tid >> 1, c = (tid & 1) * 16;
            const uint4* src = (const uint4*)(g_kh +
                ((size_t)bh * LSP + (size_t)kt * KTL + r) * DH + c);
            *(uint4*)&Ks[r][c]     = src[0];
            *(uint4*)&Ks[r][c + 8] = src[1];
        }
        // stage V tile: 32 rows(d) x 128 halves
        {
            #pragma unroll
            for (int i = tid; i < 512; i += 256) {
                const int r = i >> 4, c = (i & 15) * 8;
                *(uint4*)&Vs[r][c] = *(const uint4*)(g_vh +
                    ((size_t)bh * DH + r) * LSP + (size_t)kt * KTL + c);
            }
        }
        __syncthreads();

        // ---- S = Q x K^T : 16 n-chunks of 8 keys; LDSM.x4 per chunk ----
        float s[16][4];
        #pragma unroll
        for (int j = 0; j < 16; j++) {
            uint32_t b0, b1, b2, b3;
            ldsm_x4(b0, b1, b2, b3, &Ks[j * 8 + krow][kcol]);
            s[j][0] = s[j][1] = s[j][2] = s[j][3] = 0.f;
            mma16816(s[j][0], s[j][1], s[j][2], s[j][3],
                     qa[0], qa[1], qa[2], qa[3], b0, b1);
            mma16816(s[j][0], s[j][1], s[j][2], s[j][3],
                     qa[4], qa[5], qa[6], qa[7], b2, b3);
        }

        // ---- online softmax ----
        float nm0 = m0, nm1 = m1;
        #pragma unroll
        for (int j = 0; j < 16; j++) {
            nm0 = fmaxf(nm0, fmaxf(s[j][0], s[j][1]));
            nm1 = fmaxf(nm1, fmaxf(s[j][2], s[j][3]));
        }
        nm0 = fmaxf(nm0, __shfl_xor_sync(0xffffffffu, nm0, 1));
        nm0 = fmaxf(nm0, __shfl_xor_sync(0xffffffffu, nm0, 2));
        nm1 = fmaxf(nm1, __shfl_xor_sync(0xffffffffu, nm1, 1));
        nm1 = fmaxf(nm1, __shfl_xor_sync(0xffffffffu, nm1, 2));
        const float c0 = __expf(m0 - nm0);
        const float c1 = __expf(m1 - nm1);
        m0 = nm0; m1 = nm1;
        l0 *= c0;  l1 *= c1;
        #pragma unroll
        for (int nc = 0; nc < 4; nc++) {
            o[nc*4+0] *= c0; o[nc*4+1] *= c0;
            o[nc*4+2] *= c1; o[nc*4+3] *= c1;
        }
        // exp + pack P in place
        #pragma unroll
        for (int j = 0; j < 16; j++) {
            float e00 = __expf(s[j][0] - m0);
            float e01 = __expf(s[j][1] - m0);
            float e10 = __expf(s[j][2] - m1);
            float e11 = __expf(s[j][3] - m1);
            __half2 h0 = __floats2half2_rn(e00, e01);
            __half2 h1 = __floats2half2_rn(e10, e11);
            s[j][0] = __uint_as_float(*(uint32_t*)&h0);
            s[j][1] = __uint_as_float(*(uint32_t*)&h1);
        }

        // ---- lsum = P x ones (exact row sums of fp16 P) ----
        {
            float z0 = 0.f, z1 = 0.f, z2 = 0.f, z3 = 0.f;
            #pragma unroll
            for (int c = 0; c < 8; c++) {
                mma16816(z0, z1, z2, z3,
                         __float_as_uint(s[2*c    ][0]),
                         __float_as_uint(s[2*c    ][1]),
                         __float_as_uint(s[2*c + 1][0]),
                         __float_as_uint(s[2*c + 1][1]),
                         ONE2, ONE2);
            }
            l0 += z0;
            l1 += z2;
        }

        // ---- O += P x V : 4 n-chunks (dh), 8 k-chunks via 4 LDSM.x4 ----
        #pragma unroll
        for (int nc = 0; nc < 4; nc++) {
            float& d0 = o[nc*4+0];
            float& d1 = o[nc*4+1];
            float& d2 = o[nc*4+2];
            float& d3 = o[nc*4+3];
            #pragma unroll
            for (int cc = 0; cc < 4; cc++) {
                uint32_t v0, v1, v2, v3;
                ldsm_x4(v0, v1, v2, v3, &Vs[nc * 8 + krow][cc * 32 + kcol]);
                const int c = cc * 2;
                mma16816(d0, d1, d2, d3,
                         __float_as_uint(s[2*c    ][0]),
                         __float_as_uint(s[2*c    ][1]),
                         __float_as_uint(s[2*c + 1][0]),
                         __float_as_uint(s[2*c + 1][1]),
                         v0, v1);
                mma16816(d0, d1, d2, d3,
                         __float_as_uint(s[2*c + 2][0]),
                         __float_as_uint(s[2*c + 2][1]),
                         __float_as_uint(s[2*c + 3][0]),
                         __float_as_uint(s[2*c + 3][1]),
                         v2, v3);
            }
        }
    }

    const float inv0 = 1.0f / l0;
    const float inv1 = 1.0f / l1;

    float* ob = out + (size_t)bh * DH * LSP;
    #pragma unroll
    for (int nc = 0; nc < 4; nc++) {
        const int d = nc * 8 + tig * 2;
        ob[(size_t)(d    ) * LSP + q0 + gid    ] = o[nc*4+0] * inv0;
        ob[(size_t)(d + 1) * LSP + q0 + gid    ] = o[nc*4+1] * inv0;
        ob[(size_t)(d    ) * LSP + q0 + gid + 8] = o[nc*4+2] * inv1;
        ob[(size_t)(d + 1) * LSP + q0 + gid + 8] = o[nc*4+3] * inv1;
    }
}

// ---------------------------------------------------------------------------
extern "C" void kernel_launch(void* const* d_in, const int* in_sizes, int n_in,
                              void* d_out, int out_size)
{
    const float* x  = (const float*)d_in[0];
    const float* wq = (const float*)d_in[1];
    const float* wk = (const float*)d_in[2];
    const float* wv = (const float*)d_in[3];
    float* out = (float*)d_out;

    dim3 g1(LSP / 64, HEADS, BATCH);
    qkv_kernel<<<g1, 256>>>(x, wq, wk, wv);

    dim3 g2(LSP / QT, BH_N);
    attn_kernel<<<g2, 256>>>(out);
}

// round 6
// speedup vs baseline: 9.5850x; 1.1136x over previous
#include <cuda_runtime.h>
#include <cuda_fp16.h>
#include <cstdint>

#define BATCH 16
#define HEADS 8
#define DH 32
#define LSP 1024
#define CIN 256
#define BH_N (BATCH*HEADS)
#define QT 128            // queries per CTA (8 warps x 16)
#define KTL 128           // keys per tile
#define NKT (LSP/KTL)
#define KPAD 40           // K smem row stride (halves)
#define VPAD 136          // V smem row stride (halves)

// fp16 staging: q,k as [bh][l][d]; v as [bh][d][l]
__device__ __half g_qh[(size_t)BH_N * LSP * DH];
__device__ __half g_kh[(size_t)BH_N * LSP * DH];
__device__ __half g_vh[(size_t)BH_N * DH * LSP];

// ---------------------------------------------------------------------------
// Kernel 1: grouped 1x1 conv -> q,k,v (fp16); sine PE fused into k.
// ---------------------------------------------------------------------------
__global__ __launch_bounds__(256) void qkv_kernel(
    const float* __restrict__ x,
    const float* __restrict__ wq,
    const float* __restrict__ wk,
    const float* __restrict__ wv)
{
    __shared__ float sW[3][32][32];
    __shared__ float sx[32][64];

    const int l0  = blockIdx.x * 64;
    const int h   = blockIdx.y;
    const int b   = blockIdx.z;
    const int tid = threadIdx.x;

    for (int i = tid; i < 1024; i += 256) {
        int o = i >> 5, c = i & 31;
        int gi = (h * 32 + o) * 32 + c;
        sW[0][o][c] = wq[gi];
        sW[1][o][c] = wk[gi];
        sW[2][o][c] = wv[gi];
    }
    for (int i = tid; i < 2048; i += 256) {
        int c = i >> 6, l = i & 63;
        sx[c][l] = x[((b * CIN + h * 32 + c) * LSP) + l0 + l];
    }
    __syncthreads();

    const int l  = tid & 63;
    const int og = tid >> 6;
    const int bh = b * HEADS + h;
    const float pos = (float)(l0 + l);

    __align__(16) __half hq[8];
    __align__(16) __half hk[8];

    #pragma unroll
    for (int o2 = 0; o2 < 8; o2 += 2) {
        const int oA = og * 8 + o2;      // even channel
        const int oB = oA + 1;           // odd channel
        float aqA = 0.f, akA = 0.f, avA = 0.f;
        float aqB = 0.f, akB = 0.f, avB = 0.f;
        #pragma unroll
        for (int c = 0; c < 32; c++) {
            const float xv = sx[c][l];
            aqA = fmaf(sW[0][oA][c], xv, aqA);
            akA = fmaf(sW[1][oA][c], xv, akA);
            avA = fmaf(sW[2][oA][c], xv, avA);
            aqB = fmaf(sW[0][oB][c], xv, aqB);
            akB = fmaf(sW[1][oB][c], xv, akB);
            avB = fmaf(sW[2][oB][c], xv, avB);
        }
        const int gch = h * 32 + oA;     // even
        const float div = __expf(-0.03597789207803197f * (float)gch);
        float sv, cv;
        __sincosf(div * pos, &sv, &cv);

        hq[o2]     = __float2half(aqA);
        hq[o2 + 1] = __float2half(aqB);
        hk[o2]     = __float2half(akA + sv);
        hk[o2 + 1] = __float2half(akB + cv);
        g_vh[((size_t)bh * DH + oA) * LSP + l0 + l] = __float2half(avA);
        g_vh[((size_t)bh * DH + oB) * LSP + l0 + l] = __float2half(avB);
    }
    const size_t row = ((size_t)bh * LSP + l0 + l) * DH + og * 8;
    *(uint4*)(g_qh + row) = *(const uint4*)hq;
    *(uint4*)(g_kh + row) = *(const uint4*)hk;
}

// ---------------------------------------------------------------------------
// HMMA / LDSM / cp.async helpers
// ---------------------------------------------------------------------------
__device__ __forceinline__ void mma16816(
    float& d0, float& d1, float& d2, float& d3,
    uint32_t a0, uint32_t a1, uint32_t a2, uint32_t a3,
    uint32_t b0, uint32_t b1)
{
    asm volatile(
        "mma.sync.aligned.m16n8k16.row.col.f32.f16.f16.f32 "
        "{%0,%1,%2,%3}, {%4,%5,%6,%7}, {%8,%9}, {%0,%1,%2,%3};"
        : "+f"(d0), "+f"(d1), "+f"(d2), "+f"(d3)
        : "r"(a0), "r"(a1), "r"(a2), "r"(a3), "r"(b0), "r"(b1));
}

__device__ __forceinline__ void ldsm_x4(uint32_t& r0, uint32_t& r1,
                                        uint32_t& r2, uint32_t& r3,
                                        const void* p)
{
    uint32_t a = (uint32_t)__cvta_generic_to_shared(p);
    asm volatile(
        "ldmatrix.sync.aligned.m8n8.x4.shared.b16 {%0,%1,%2,%3}, [%4];"
        : "=r"(r0), "=r"(r1), "=r"(r2), "=r"(r3) : "r"(a));
}

__device__ __forceinline__ void cp16(void* smem, const void* gmem)
{
    uint32_t a = (uint32_t)__cvta_generic_to_shared(smem);
    asm volatile("cp.async.cg.shared.global [%0], [%1], 16;"
                 :: "r"(a), "l"(gmem));
}

// exp2 of two packed args: t1(hi), t0(lo) in f32 -> half2(e^..)
__device__ __forceinline__ uint32_t exp2_f16x2(float t0, float t1)
{
    uint32_t p;
    asm("cvt.rn.f16x2.f32 %0, %1, %2;" : "=r"(p) : "f"(t1), "f"(t0));
    asm("ex2.approx.f16x2 %0, %0;" : "+r"(p));
    return p;
}

// ---------------------------------------------------------------------------
// Kernel 2: register-fragment flash attention, HMMA + LDSM + cp.async
// double-buffered K/V staging + f16x2 exp.
// ---------------------------------------------------------------------------
__global__ __launch_bounds__(256, 2) void attn_kernel(float* __restrict__ out)
{
    __shared__ __half Ks[2][KTL][KPAD];   // [buf][key][d]
    __shared__ __half Vs[2][DH][VPAD];    // [buf][d][key]

    const int tid  = threadIdx.x;
    const int wid  = tid >> 5;
    const int lane = tid & 31;
    const int gid  = lane >> 2;   // 0..7
    const int tig  = lane & 3;    // 0..3
    const int bh   = blockIdx.y;
    const int q0   = blockIdx.x * QT + wid * 16;
    const uint32_t ONE2 = 0x3C003C00u;    // half2(1,1)
    const float L2E = 1.4426950408889634f;

    const __half* kbase = g_kh + (size_t)bh * LSP * DH;
    const __half* vbase = g_vh + (size_t)bh * DH * LSP;

    // staging coordinates (per thread)
    const int kr = tid >> 1, kc = (tid & 1) * 16;     // K: 2x16B per thread
    const int vr0 = tid >> 4,        vc0 = (tid & 15) * 8;
    const int vr1 = (tid + 256) >> 4, vc1 = ((tid + 256) & 15) * 8;

    // Q fragments
    uint32_t qa[8];
    {
        const __half* qb = g_qh + ((size_t)bh * LSP + q0) * DH;
        #pragma unroll
        for (int kk = 0; kk < 2; kk++) {
            qa[kk*4+0] = *(const uint32_t*)(qb + (gid    ) * DH + kk*16     + tig*2);
            qa[kk*4+1] = *(const uint32_t*)(qb + (gid + 8) * DH + kk*16     + tig*2);
            qa[kk*4+2] = *(const uint32_t*)(qb + (gid    ) * DH + kk*16 + 8 + tig*2);
            qa[kk*4+3] = *(const uint32_t*)(qb + (gid + 8) * DH + kk*16 + 8 + tig*2);
        }
    }

    // prefetch tile 0
    {
        cp16(&Ks[0][kr][kc],     kbase + (size_t)kr * DH + kc);
        cp16(&Ks[0][kr][kc + 8], kbase + (size_t)kr * DH + kc + 8);
        cp16(&Vs[0][vr0][vc0],   vbase + (size_t)vr0 * LSP + vc0);
        cp16(&Vs[0][vr1][vc1],   vbase + (size_t)vr1 * LSP + vc1);
        asm volatile("cp.async.commit_group;" ::: "memory");
    }

    float o[16];
    #pragma unroll
    for (int i = 0; i < 16; i++) o[i] = 0.f;
    float m0 = -1e30f, m1 = -1e30f, l0 = 0.f, l1 = 0.f;

    const int krow = lane & 7;
    const int kcol = ((lane >> 3) & 3) * 8;

    for (int kt = 0; kt < NKT; kt++) {
        const int buf = kt & 1;
        // prefetch next tile into the other buffer
        if (kt + 1 < NKT) {
            const size_t koff = (size_t)(kt + 1) * KTL;
            cp16(&Ks[buf^1][kr][kc],     kbase + (koff + kr) * DH + kc);
            cp16(&Ks[buf^1][kr][kc + 8], kbase + (koff + kr) * DH + kc + 8);
            cp16(&Vs[buf^1][vr0][vc0],   vbase + (size_t)vr0 * LSP + koff + vc0);
            cp16(&Vs[buf^1][vr1][vc1],   vbase + (size_t)vr1 * LSP + koff + vc1);
            asm volatile("cp.async.commit_group;" ::: "memory");
            asm volatile("cp.async.wait_group 1;" ::: "memory");
        } else {
            asm volatile("cp.async.wait_group 0;" ::: "memory");
        }
        __syncthreads();

        // ---- S = Q x K^T ----
        float s[16][4];
        #pragma unroll
        for (int j = 0; j < 16; j++) {
            uint32_t b0, b1, b2, b3;
            ldsm_x4(b0, b1, b2, b3, &Ks[buf][j * 8 + krow][kcol]);
            s[j][0] = s[j][1] = s[j][2] = s[j][3] = 0.f;
            mma16816(s[j][0], s[j][1], s[j][2], s[j][3],
                     qa[0], qa[1], qa[2], qa[3], b0, b1);
            mma16816(s[j][0], s[j][1], s[j][2], s[j][3],
                     qa[4], qa[5], qa[6], qa[7], b2, b3);
        }

        // ---- online softmax ----
        float nm0 = m0, nm1 = m1;
        #pragma unroll
        for (int j = 0; j < 16; j++) {
            nm0 = fmaxf(nm0, fmaxf(s[j][0], s[j][1]));
            nm1 = fmaxf(nm1, fmaxf(s[j][2], s[j][3]));
        }
        nm0 = fmaxf(nm0, __shfl_xor_sync(0xffffffffu, nm0, 1));
        nm0 = fmaxf(nm0, __shfl_xor_sync(0xffffffffu, nm0, 2));
        nm1 = fmaxf(nm1, __shfl_xor_sync(0xffffffffu, nm1, 1));
        nm1 = fmaxf(nm1, __shfl_xor_sync(0xffffffffu, nm1, 2));
        const float c0 = __expf(m0 - nm0);
        const float c1 = __expf(m1 - nm1);
        m0 = nm0; m1 = nm1;
        l0 *= c0;  l1 *= c1;
        #pragma unroll
        for (int nc = 0; nc < 4; nc++) {
            o[nc*4+0] *= c0; o[nc*4+1] *= c0;
            o[nc*4+2] *= c1; o[nc*4+3] *= c1;
        }
        // P = exp2((s-m)*log2e) via f16x2 MUFU, packed in place
        const float nb0 = -m0 * L2E;
        const float nb1 = -m1 * L2E;
        #pragma unroll
        for (int j = 0; j < 16; j++) {
            float t00 = fmaf(s[j][0], L2E, nb0);
            float t01 = fmaf(s[j][1], L2E, nb0);
            float t10 = fmaf(s[j][2], L2E, nb1);
            float t11 = fmaf(s[j][3], L2E, nb1);
            s[j][0] = __uint_as_float(exp2_f16x2(t00, t01));
            s[j][1] = __uint_as_float(exp2_f16x2(t10, t11));
        }

        // ---- lsum = P x ones (two 4-deep chains) ----
        {
            float za0 = 0.f, za1 = 0.f, za2 = 0.f, za3 = 0.f;
            float zb0 = 0.f, zb1 = 0.f, zb2 = 0.f, zb3 = 0.f;
            #pragma unroll
            for (int c = 0; c < 4; c++) {
                mma16816(za0, za1, za2, za3,
                         __float_as_uint(s[2*c    ][0]),
                         __float_as_uint(s[2*c    ][1]),
                         __float_as_uint(s[2*c + 1][0]),
                         __float_as_uint(s[2*c + 1][1]),
                         ONE2, ONE2);
                mma16816(zb0, zb1, zb2, zb3,
                         __float_as_uint(s[8 + 2*c    ][0]),
                         __float_as_uint(s[8 + 2*c    ][1]),
                         __float_as_uint(s[8 + 2*c + 1][0]),
                         __float_as_uint(s[8 + 2*c + 1][1]),
                         ONE2, ONE2);
            }
            l0 += za0 + zb0;
            l1 += za2 + zb2;
        }

        // ---- O += P x V ----
        #pragma unroll
        for (int nc = 0; nc < 4; nc++) {
            float& d0 = o[nc*4+0];
            float& d1 = o[nc*4+1];
            float& d2 = o[nc*4+2];
            float& d3 = o[nc*4+3];
            #pragma unroll
            for (int cc = 0; cc < 4; cc++) {
                uint32_t v0, v1, v2, v3;
                ldsm_x4(v0, v1, v2, v3, &Vs[buf][nc * 8 + krow][cc * 32 + kcol]);
                const int c = cc * 2;
                mma16816(d0, d1, d2, d3,
                         __float_as_uint(s[2*c    ][0]),
                         __float_as_uint(s[2*c    ][1]),
                         __float_as_uint(s[2*c + 1][0]),
                         __float_as_uint(s[2*c + 1][1]),
                         v0, v1);
                mma16816(d0, d1, d2, d3,
                         __float_as_uint(s[2*c + 2][0]),
                         __float_as_uint(s[2*c + 2][1]),
                         __float_as_uint(s[2*c + 3][0]),
                         __float_as_uint(s[2*c + 3][1]),
                         v2, v3);
            }
        }
        __syncthreads();
    }

    const float inv0 = 1.0f / l0;
    const float inv1 = 1.0f / l1;

    float* ob = out + (size_t)bh * DH * LSP;
    #pragma unroll
    for (int nc = 0; nc < 4; nc++) {
        const int d = nc * 8 + tig * 2;
        ob[(size_t)(d    ) * LSP + q0 + gid    ] = o[nc*4+0] * inv0;
        ob[(size_t)(d + 1) * LSP + q0 + gid    ] = o[nc*4+1] * inv0;
        ob[(size_t)(d    ) * LSP + q0 + gid + 8] = o[nc*4+2] * inv1;
        ob[(size_t)(d + 1) * LSP + q0 + gid + 8] = o[nc*4+3] * inv1;
    }
}

// ---------------------------------------------------------------------------
extern "C" void kernel_launch(void* const* d_in, const int* in_sizes, int n_in,
                              void* d_out, int out_size)
{
    const float* x  = (const float*)d_in[0];
    const float* wq = (const float*)d_in[1];
    const float* wk = (const float*)d_in[2];
    const float* wv = (const float*)d_in[3];
    float* out = (float*)d_out;

    dim3 g1(LSP / 64, HEADS, BATCH);
    qkv_kernel<<<g1, 256>>>(x, wq, wk, wv);

    dim3 g2(LSP / QT, BH_N);
    attn_kernel<<<g2, 256>>>(out);
}

// round 7
// speedup vs baseline: 12.6427x; 1.3190x over previous
#include <cuda_runtime.h>
#include <cuda_fp16.h>
#include <cstdint>

#define BATCH 16
#define HEADS 8
#define DH 32
#define LSP 1024
#define CIN 256
#define BH_N (BATCH*HEADS)
#define QT 128            // queries per CTA in attn (8 warps x 16)
#define KTL 128           // keys per tile
#define NKT (LSP/KTL)
#define KPAD 40           // K smem row stride (halves)
#define VPAD 136          // V smem row stride (halves)
#define XLT 256           // l-tile for qkv GEMM
#define XPAD 264          // Xs row stride (halves)
#define WPAD 40           // Ws row stride (halves)

// fp16 staging: q,k as [bh][l][d]; v as [bh][d][l]
__device__ __half g_qh[(size_t)BH_N * LSP * DH];
__device__ __half g_kh[(size_t)BH_N * LSP * DH];
__device__ __half g_vh[(size_t)BH_N * DH * LSP];

// ---------------------------------------------------------------------------
// HMMA / LDSM / cp.async helpers
// ---------------------------------------------------------------------------
__device__ __forceinline__ void mma16816(
    float& d0, float& d1, float& d2, float& d3,
    uint32_t a0, uint32_t a1, uint32_t a2, uint32_t a3,
    uint32_t b0, uint32_t b1)
{
    asm volatile(
        "mma.sync.aligned.m16n8k16.row.col.f32.f16.f16.f32 "
        "{%0,%1,%2,%3}, {%4,%5,%6,%7}, {%8,%9}, {%0,%1,%2,%3};"
        : "+f"(d0), "+f"(d1), "+f"(d2), "+f"(d3)
        : "r"(a0), "r"(a1), "r"(a2), "r"(a3), "r"(b0), "r"(b1));
}

__device__ __forceinline__ void ldsm_x4(uint32_t& r0, uint32_t& r1,
                                        uint32_t& r2, uint32_t& r3,
                                        const void* p)
{
    uint32_t a = (uint32_t)__cvta_generic_to_shared(p);
    asm volatile(
        "ldmatrix.sync.aligned.m8n8.x4.shared.b16 {%0,%1,%2,%3}, [%4];"
        : "=r"(r0), "=r"(r1), "=r"(r2), "=r"(r3) : "r"(a));
}

__device__ __forceinline__ void ldsm_x4_trans(uint32_t& r0, uint32_t& r1,
                                              uint32_t& r2, uint32_t& r3,
                                              const void* p)
{
    uint32_t a = (uint32_t)__cvta_generic_to_shared(p);
    asm volatile(
        "ldmatrix.sync.aligned.m8n8.x4.trans.shared.b16 {%0,%1,%2,%3}, [%4];"
        : "=r"(r0), "=r"(r1), "=r"(r2), "=r"(r3) : "r"(a));
}

__device__ __forceinline__ void cp16(void* smem, const void* gmem)
{
    uint32_t a = (uint32_t)__cvta_generic_to_shared(smem);
    asm volatile("cp.async.cg.shared.global [%0], [%1], 16;"
                 :: "r"(a), "l"(gmem));
}

__device__ __forceinline__ uint32_t exp2_f16x2(float t0, float t1)
{
    uint32_t p;
    asm("cvt.rn.f16x2.f32 %0, %1, %2;" : "=r"(p) : "f"(t1), "f"(t0));
    asm("ex2.approx.f16x2 %0, %0;" : "+r"(p));
    return p;
}

// ---------------------------------------------------------------------------
// Kernel 1: grouped 1x1 conv as HMMA GEMM. CTA = (l-tile 256, bh).
// Out[l][o] = sum_c X[c][l] * W[o][c] ; PE fused into K epilogue.
// ---------------------------------------------------------------------------
__global__ __launch_bounds__(256) void qkv_kernel(
    const float* __restrict__ x,
    const float* __restrict__ wq,
    const float* __restrict__ wk,
    const float* __restrict__ wv)
{
    __shared__ __half Xs[32][XPAD];      // [c][l]
    __shared__ __half Ws[3][32][WPAD];   // [mat][o][c]

    const int l0  = blockIdx.x * XLT;
    const int bh  = blockIdx.y;
    const int b   = bh >> 3;
    const int h   = bh & 7;
    const int tid = threadIdx.x;
    const int wid = tid >> 5;
    const int lane = tid & 31;
    const int gid = lane >> 2;
    const int tig = lane & 3;

    // stage x tile [32 c][256 l] as fp16
    for (int idx = tid; idx < 32 * 64; idx += 256) {
        const int c  = idx >> 6;
        const int l4 = (idx & 63) * 4;
        const float4 v = *(const float4*)(x +
            ((size_t)(b * CIN + h * 32 + c) * LSP) + l0 + l4);
        __half2 h0 = __floats2half2_rn(v.x, v.y);
        __half2 h1 = __floats2half2_rn(v.z, v.w);
        *(__half2*)&Xs[c][l4]     = h0;
        *(__half2*)&Xs[c][l4 + 2] = h1;
    }
    // stage weights (3 x 32x32) as fp16
    {
        const float* wp[3] = {wq, wk, wv};
        for (int idx = tid; idx < 3072; idx += 256) {
            const int mat = idx >> 10;
            const int o   = (idx >> 5) & 31;
            const int c   = idx & 31;
            Ws[mat][o][c] = __float2half(wp[mat][(h * 32 + o) * 32 + c]);
        }
    }
    __syncthreads();

    // per-thread LDSM coords
    const int krow = lane & 7;
    const int kcol = ((lane >> 3) & 3) * 8;
    // A trans coords: row = ks*16 + ((lane>>4)?8:0) + (lane&7), col = m + ((lane>>3)&1)*8
    const int arow_g = ((lane >> 4) << 3) + (lane & 7);
    const int acol_g = ((lane >> 3) & 1) * 8;

    // PE divisors per n-chunk (ch even = h*32 + nc*8 + tig*2)
    float divs[4];
    #pragma unroll
    for (int nc = 0; nc < 4; nc++)
        divs[nc] = __expf(-0.03597789207803197f *
                          (float)(h * 32 + nc * 8 + tig * 2));

    const int m0 = wid * 32;

    #pragma unroll
    for (int mc = 0; mc < 2; mc++) {
        const int m = m0 + mc * 16;
        // A fragments for ksteps 0,1
        uint32_t a[2][4];
        #pragma unroll
        for (int ks = 0; ks < 2; ks++)
            ldsm_x4_trans(a[ks][0], a[ks][1], a[ks][2], a[ks][3],
                          &Xs[ks * 16 + arow_g][m + acol_g]);

        #pragma unroll
        for (int mat = 0; mat < 3; mat++) {
            #pragma unroll
            for (int nc = 0; nc < 4; nc++) {
                uint32_t b0, b1, b2, b3;
                ldsm_x4(b0, b1, b2, b3, &Ws[mat][nc * 8 + krow][kcol]);
                float d0 = 0.f, d1 = 0.f, d2 = 0.f, d3 = 0.f;
                mma16816(d0, d1, d2, d3,
                         a[0][0], a[0][1], a[0][2], a[0][3], b0, b1);
                mma16816(d0, d1, d2, d3,
                         a[1][0], a[1][1], a[1][2], a[1][3], b2, b3);

                const int lrow = l0 + m + gid;      // fragment rows: lrow, lrow+8
                const int dch  = nc * 8 + tig * 2;  // cols: dch, dch+1

                if (mat == 0) {
                    __half2 v0 = __floats2half2_rn(d0, d1);
                    __half2 v1 = __floats2half2_rn(d2, d3);
                    *(__half2*)(g_qh + ((size_t)bh * LSP + lrow)     * DH + dch) = v0;
                    *(__half2*)(g_qh + ((size_t)bh * LSP + lrow + 8) * DH + dch) = v1;
                } else if (mat == 1) {
                    float s0, c0, s1, c1;
                    __sincosf(divs[nc] * (float)lrow,       &s0, &c0);
                    __sincosf(divs[nc] * (float)(lrow + 8), &s1, &c1);
                    __half2 v0 = __floats2half2_rn(d0 + s0, d1 + c0);
                    __half2 v1 = __floats2half2_rn(d2 + s1, d3 + c1);
                    *(__half2*)(g_kh + ((size_t)bh * LSP + lrow)     * DH + dch) = v0;
                    *(__half2*)(g_kh + ((size_t)bh * LSP + lrow + 8) * DH + dch) = v1;
                } else {
                    __half* vb = g_vh + (size_t)bh * DH * LSP;
                    vb[(size_t)(dch    ) * LSP + lrow    ] = __float2half(d0);
                    vb[(size_t)(dch + 1) * LSP + lrow    ] = __float2half(d1);
                    vb[(size_t)(dch    ) * LSP + lrow + 8] = __float2half(d2);
                    vb[(size_t)(dch + 1) * LSP + lrow + 8] = __float2half(d3);
                }
            }
        }
    }
}

// ---------------------------------------------------------------------------
// Kernel 2: register-fragment flash attention, HMMA + LDSM + cp.async
// double-buffered K/V staging + f16x2 exp. (unchanged from R6)
// ---------------------------------------------------------------------------
__global__ __launch_bounds__(256, 2) void attn_kernel(float* __restrict__ out)
{
    __shared__ __half Ks[2][KTL][KPAD];   // [buf][key][d]
    __shared__ __half Vs[2][DH][VPAD];    // [buf][d][key]

    const int tid  = threadIdx.x;
    const int wid  = tid >> 5;
    const int lane = tid & 31;
    const int gid  = lane >> 2;
    const int tig  = lane & 3;
    const int bh   = blockIdx.y;
    const int q0   = blockIdx.x * QT + wid * 16;
    const uint32_t ONE2 = 0x3C003C00u;
    const float L2E = 1.4426950408889634f;

    const __half* kbase = g_kh + (size_t)bh * LSP * DH;
    const __half* vbase = g_vh + (size_t)bh * DH * LSP;

    const int kr = tid >> 1, kc = (tid & 1) * 16;
    const int vr0 = tid >> 4,         vc0 = (tid & 15) * 8;
    const int vr1 = (tid + 256) >> 4, vc1 = ((tid + 256) & 15) * 8;

    uint32_t qa[8];
    {
        const __half* qb = g_qh + ((size_t)bh * LSP + q0) * DH;
        #pragma unroll
        for (int kk = 0; kk < 2; kk++) {
            qa[kk*4+0] = *(const uint32_t*)(qb + (gid    ) * DH + kk*16     + tig*2);
            qa[kk*4+1] = *(const uint32_t*)(qb + (gid + 8) * DH + kk*16     + tig*2);
            qa[kk*4+2] = *(const uint32_t*)(qb + (gid    ) * DH + kk*16 + 8 + tig*2);
            qa[kk*4+3] = *(const uint32_t*)(qb + (gid + 8) * DH + kk*16 + 8 + tig*2);
        }
    }

    {
        cp16(&Ks[0][kr][kc],     kbase + (size_t)kr * DH + kc);
        cp16(&Ks[0][kr][kc + 8], kbase + (size_t)kr * DH + kc + 8);
        cp16(&Vs[0][vr0][vc0],   vbase + (size_t)vr0 * LSP + vc0);
        cp16(&Vs[0][vr1][vc1],   vbase + (size_t)vr1 * LSP + vc1);
        asm volatile("cp.async.commit_group;" ::: "memory");
    }

    float o[16];
    #pragma unroll
    for (int i = 0; i < 16; i++) o[i] = 0.f;
    float m0 = -1e30f, m1 = -1e30f, l0 = 0.f, l1 = 0.f;

    const int krow = lane & 7;
    const int kcol = ((lane >> 3) & 3) * 8;

    for (int kt = 0; kt < NKT; kt++) {
        const int buf = kt & 1;
        if (kt + 1 < NKT) {
            const size_t koff = (size_t)(kt + 1) * KTL;
            cp16(&Ks[buf^1][kr][kc],     kbase + (koff + kr) * DH + kc);
            cp16(&Ks[buf^1][kr][kc + 8], kbase + (koff + kr) * DH + kc + 8);
            cp16(&Vs[buf^1][vr0][vc0],   vbase + (size_t)vr0 * LSP + koff + vc0);
            cp16(&Vs[buf^1][vr1][vc1],   vbase + (size_t)vr1 * LSP + koff + vc1);
            asm volatile("cp.async.commit_group;" ::: "memory");
            asm volatile("cp.async.wait_group 1;" ::: "memory");
        } else {
            asm volatile("cp.async.wait_group 0;" ::: "memory");
        }
        __syncthreads();

        float s[16][4];
        #pragma unroll
        for (int j = 0; j < 16; j++) {
            uint32_t b0, b1, b2, b3;
            ldsm_x4(b0, b1, b2, b3, &Ks[buf][j * 8 + krow][kcol]);
            s[j][0] = s[j][1] = s[j][2] = s[j][3] = 0.f;
            mma16816(s[j][0], s[j][1], s[j][2], s[j][3],
                     qa[0], qa[1], qa[2], qa[3], b0, b1);
            mma16816(s[j][0], s[j][1], s[j][2], s[j][3],
                     qa[4], qa[5], qa[6], qa[7], b2, b3);
        }

        float nm0 = m0, nm1 = m1;
        #pragma unroll
        for (int j = 0; j < 16; j++) {
            nm0 = fmaxf(nm0, fmaxf(s[j][0], s[j][1]));
            nm1 = fmaxf(nm1, fmaxf(s[j][2], s[j][3]));
        }
        nm0 = fmaxf(nm0, __shfl_xor_sync(0xffffffffu, nm0, 1));
        nm0 = fmaxf(nm0, __shfl_xor_sync(0xffffffffu, nm0, 2));
        nm1 = fmaxf(nm1, __shfl_xor_sync(0xffffffffu, nm1, 1));
        nm1 = fmaxf(nm1, __shfl_xor_sync(0xffffffffu, nm1, 2));
        const float c0 = __expf(m0 - nm0);
        const float c1 = __expf(m1 - nm1);
        m0 = nm0; m1 = nm1;
        l0 *= c0;  l1 *= c1;
        #pragma unroll
        for (int nc = 0; nc < 4; nc++) {
            o[nc*4+0] *= c0; o[nc*4+1] *= c0;
            o[nc*4+2] *= c1; o[nc*4+3] *= c1;
        }
        const float nb0 = -m0 * L2E;
        const float nb1 = -m1 * L2E;
        #pragma unroll
        for (int j = 0; j < 16; j++) {
            float t00 = fmaf(s[j][0], L2E, nb0);
            float t01 = fmaf(s[j][1], L2E, nb0);
            float t10 = fmaf(s[j][2], L2E, nb1);
            float t11 = fmaf(s[j][3], L2E, nb1);
            s[j][0] = __uint_as_float(exp2_f16x2(t00, t01));
            s[j][1] = __uint_as_float(exp2_f16x2(t10, t11));
        }

        {
            float za0 = 0.f, za1 = 0.f, za2 = 0.f, za3 = 0.f;
            float zb0 = 0.f, zb1 = 0.f, zb2 = 0.f, zb3 = 0.f;
            #pragma unroll
            for (int c = 0; c < 4; c++) {
                mma16816(za0, za1, za2, za3,
                         __float_as_uint(s[2*c    ][0]),
                         __float_as_uint(s[2*c    ][1]),
                         __float_as_uint(s[2*c + 1][0]),
                         __float_as_uint(s[2*c + 1][1]),
                         ONE2, ONE2);
                mma16816(zb0, zb1, zb2, zb3,
                         __float_as_uint(s[8 + 2*c    ][0]),
                         __float_as_uint(s[8 + 2*c    ][1]),
                         __float_as_uint(s[8 + 2*c + 1][0]),
                         __float_as_uint(s[8 + 2*c + 1][1]),
                         ONE2, ONE2);
            }
            l0 += za0 + zb0;
            l1 += za2 + zb2;
        }

        #pragma unroll
        for (int nc = 0; nc < 4; nc++) {
            float& d0 = o[nc*4+0];
            float& d1 = o[nc*4+1];
            float& d2 = o[nc*4+2];
            float& d3 = o[nc*4+3];
            #pragma unroll
            for (int cc = 0; cc < 4; cc++) {
                uint32_t v0, v1, v2, v3;
                ldsm_x4(v0, v1, v2, v3, &Vs[buf][nc * 8 + krow][cc * 32 + kcol]);
                const int c = cc * 2;
                mma16816(d0, d1, d2, d3,
                         __float_as_uint(s[2*c    ][0]),
                         __float_as_uint(s[2*c    ][1]),
                         __float_as_uint(s[2*c + 1][0]),
                         __float_as_uint(s[2*c + 1][1]),
                         v0, v1);
                mma16816(d0, d1, d2, d3,
                         __float_as_uint(s[2*c + 2][0]),
                         __float_as_uint(s[2*c + 2][1]),
                         __float_as_uint(s[2*c + 3][0]),
                         __float_as_uint(s[2*c + 3][1]),
                         v2, v3);
            }
        }
        __syncthreads();
    }

    const float inv0 = 1.0f / l0;
    const float inv1 = 1.0f / l1;

    float* ob = out + (size_t)bh * DH * LSP;
    #pragma unroll
    for (int nc = 0; nc < 4; nc++) {
        const int d = nc * 8 + tig * 2;
        ob[(size_t)(d    ) * LSP + q0 + gid    ] = o[nc*4+0] * inv0;
        ob[(size_t)(d + 1) * LSP + q0 + gid    ] = o[nc*4+1] * inv0;
        ob[(size_t)(d    ) * LSP + q0 + gid + 8] = o[nc*4+2] * inv1;
        ob[(size_t)(d + 1) * LSP + q0 + gid + 8] = o[nc*4+3] * inv1;
    }
}

// ---------------------------------------------------------------------------
extern "C" void kernel_launch(void* const* d_in, const int* in_sizes, int n_in,
                              void* d_out, int out_size)
{
    const float* x  = (const float*)d_in[0];
    const float* wq = (const float*)d_in[1];
    const float* wk = (const float*)d_in[2];
    const float* wv = (const float*)d_in[3];
    float* out = (float*)d_out;

    dim3 g1(LSP / XLT, BH_N);
    qkv_kernel<<<g1, 256>>>(x, wq, wk, wv);

    dim3 g2(LSP / QT, BH_N);
    attn_kernel<<<g2, 256>>>(out);
}